// round 2
// baseline (speedup 1.0000x reference)
#include <cuda_runtime.h>
#include <cstdint>

#define NCOEF 25
#define TILE_ROWS 128
#define THREADS 128
#define TILE_FLOATS (TILE_ROWS * NCOEF)   // 3200
#define TILE_F4 (TILE_FLOATS / 4)         // 800

__device__ __forceinline__ void cp_async16(uint32_t s, const float4* g) {
    asm volatile("cp.async.cg.shared.global [%0], [%1], 16;" :: "r"(s), "l"(g));
}

__global__ __launch_bounds__(THREADS)
void parcor_pipe_kernel(const float* __restrict__ in, float* __restrict__ out,
                        int nrows, int ntiles)
{
    __shared__ float sbuf[2][TILE_FLOATS];
    const int tid = threadIdx.x;
    const int nblocks = gridDim.x;

    // Prefetch one tile into buffer `stage`. Full tiles: async 16B copies.
    // Partial tail tile: blocking scalar loads (still followed by an empty
    // commit_group so wait_group counts stay consistent).
    auto prefetch = [&](int tile, int stage) {
        long long base = (long long)tile * TILE_FLOATS;
        int vr = nrows - tile * TILE_ROWS;           // rows in this tile
        if (vr >= TILE_ROWS) {
            const float4* g = reinterpret_cast<const float4*>(in + base);
            uint32_t s = (uint32_t)__cvta_generic_to_shared(&sbuf[stage][0]);
            #pragma unroll
            for (int i = 0; i < 7; ++i) {
                int idx = tid + i * THREADS;
                if (idx < TILE_F4) cp_async16(s + idx * 16, g + idx);
            }
        } else {
            int vfloat = vr * NCOEF;
            for (int f = tid; f < vfloat; f += THREADS)
                sbuf[stage][f] = in[base + f];
        }
        asm volatile("cp.async.commit_group;");
    };

    int t = blockIdx.x;
    if (t >= ntiles) return;

    int stage = 0;
    prefetch(t, 0);

    for (; t < ntiles; t += nblocks) {
        int tnext = t + nblocks;
        if (tnext < ntiles) {
            prefetch(tnext, stage ^ 1);               // keep DRAM busy during compute
            asm volatile("cp.async.wait_group 1;");   // current tile's group done
        } else {
            asm volatile("cp.async.wait_group 0;");
        }
        __syncthreads();

        // ---- compute: one row per thread, fully in registers ----
        const int row = t * TILE_ROWS + tid;
        const bool active = row < nrows;
        float a[NCOEF];
        if (active) {
            #pragma unroll
            for (int j = 0; j < NCOEF; ++j) a[j] = sbuf[stage][tid * NCOEF + j];

            #pragma unroll
            for (int m = 2; m <= NCOEF - 1; ++m) {
                const float km = a[m];                // a[m] == k[m], untouched
                int i = 1, j = m - 1;
                #pragma unroll
                for (; i < j; ++i, --j) {
                    float ai = a[i], aj = a[j];
                    a[i] = fmaf(km, aj, ai);
                    a[j] = fmaf(km, ai, aj);
                }
                if (i == j) {
                    float ai = a[i];
                    a[i] = fmaf(km, ai, ai);
                }
            }
            // writeback: own row only -> no barrier needed between read & write
            #pragma unroll
            for (int j = 0; j < NCOEF; ++j) sbuf[stage][tid * NCOEF + j] = a[j];
        }
        __syncthreads();

        // ---- coalesced float4 store ----
        {
            long long base = (long long)t * TILE_FLOATS;
            int vr = nrows - t * TILE_ROWS;
            if (vr >= TILE_ROWS) {
                float4* g = reinterpret_cast<float4*>(out + base);
                const float4* sp = reinterpret_cast<const float4*>(&sbuf[stage][0]);
                #pragma unroll
                for (int i = 0; i < 7; ++i) {
                    int idx = tid + i * THREADS;
                    if (idx < TILE_F4) g[idx] = sp[idx];
                }
            } else {
                int vfloat = vr * NCOEF;
                for (int f = tid; f < vfloat; f += THREADS)
                    out[base + f] = sbuf[stage][f];
            }
        }
        __syncthreads();   // orders store-reads of sbuf[stage] before the
                           // prefetch that reuses it two iterations from now
        stage ^= 1;
    }
}

extern "C" void kernel_launch(void* const* d_in, const int* in_sizes, int n_in,
                              void* d_out, int out_size)
{
    const float* k = (const float*)d_in[0];
    float* out = (float*)d_out;
    int nrows = in_sizes[0] / NCOEF;                  // 2097152 on the bench shape
    int ntiles = (nrows + TILE_ROWS - 1) / TILE_ROWS;

    int nblocks = 148 * 9;                            // ~smem-limited residency
    if (nblocks > ntiles) nblocks = ntiles;

    parcor_pipe_kernel<<<nblocks, THREADS>>>(k, out, nrows, ntiles);
}